// round 2
// baseline (speedup 1.0000x reference)
#include <cuda_runtime.h>
#include <cuda_bf16.h>
#include <cstddef>

// Problem constants
#define BB 4
#define TT 2048
#define CC 1024
#define NH 16
#define HD 64

// ---------------- scratch (device globals; no allocations allowed) ----------
__device__ float g_qkv[(size_t)BB * TT * 3 * CC];   // [B,T,3C]  ~100.7 MB
__device__ float g_y  [(size_t)BB * TT * CC];       // [B,T,C]   ~33.6 MB

// ---------------- tiled fp32 GEMM: C = A @ B + bias -------------------------
// A: [M,K] row-major, B: [K,N] row-major, bias: [N]
// BM=128, BN=128, BK=8, 256 threads, 8x8 per thread. M,N,K all multiples.
#define GBM 128
#define GBN 128
#define GBK 8
#define GTM 8
#define GTN 8

__device__ __forceinline__ void gemm_body(
    const float* __restrict__ A, const float* __restrict__ B,
    const float* __restrict__ bias, float* __restrict__ C,
    int M, int N, int K)
{
    __shared__ float As[GBK][GBM];
    __shared__ float Bs[GBK][GBN];

    const int tid = threadIdx.x;
    const int bx = blockIdx.x;   // N tiles
    const int by = blockIdx.y;   // M tiles

    const float* Ab = A + (size_t)by * GBM * K;
    const float* Bb = B + (size_t)bx * GBN;

    // load mapping: A tile 128x8 -> 256 float4 loads; each thread 1
    const int aRow  = tid >> 1;          // 0..127
    const int aCol4 = (tid & 1) * 4;     // 0 or 4
    // B tile 8x128 -> 256 float4 loads; each thread 1
    const int bRow  = tid >> 5;          // 0..7
    const int bCol4 = (tid & 31) * 4;    // 0..124

    const int tRow = (tid >> 4) * GTM;   // 0..120
    const int tCol = (tid & 15) * GTN;   // 0..120

    float acc[GTM][GTN];
    #pragma unroll
    for (int i = 0; i < GTM; i++)
        #pragma unroll
        for (int j = 0; j < GTN; j++) acc[i][j] = 0.f;

    for (int k0 = 0; k0 < K; k0 += GBK) {
        float4 av = *(const float4*)(Ab + (size_t)aRow * K + k0 + aCol4);
        As[aCol4 + 0][aRow] = av.x;
        As[aCol4 + 1][aRow] = av.y;
        As[aCol4 + 2][aRow] = av.z;
        As[aCol4 + 3][aRow] = av.w;
        float4 bv = *(const float4*)(Bb + (size_t)(k0 + bRow) * N + bCol4);
        *(float4*)&Bs[bRow][bCol4] = bv;
        __syncthreads();

        #pragma unroll
        for (int kk = 0; kk < GBK; kk++) {
            float ra[GTM], rb[GTN];
            #pragma unroll
            for (int i = 0; i < GTM; i += 4) {
                float4 v = *(const float4*)&As[kk][tRow + i];
                ra[i] = v.x; ra[i+1] = v.y; ra[i+2] = v.z; ra[i+3] = v.w;
            }
            #pragma unroll
            for (int j = 0; j < GTN; j += 4) {
                float4 v = *(const float4*)&Bs[kk][tCol + j];
                rb[j] = v.x; rb[j+1] = v.y; rb[j+2] = v.z; rb[j+3] = v.w;
            }
            #pragma unroll
            for (int i = 0; i < GTM; i++)
                #pragma unroll
                for (int j = 0; j < GTN; j++)
                    acc[i][j] += ra[i] * rb[j];
        }
        __syncthreads();
    }

    // epilogue: add bias, store float4
    #pragma unroll
    for (int i = 0; i < GTM; i++) {
        const size_t row = (size_t)by * GBM + tRow + i;
        #pragma unroll
        for (int j = 0; j < GTN; j += 4) {
            const int col = bx * GBN + tCol + j;
            float4 o;
            o.x = acc[i][j + 0] + bias[col + 0];
            o.y = acc[i][j + 1] + bias[col + 1];
            o.z = acc[i][j + 2] + bias[col + 2];
            o.w = acc[i][j + 3] + bias[col + 3];
            *(float4*)(C + row * N + col) = o;
        }
    }
}

__global__ __launch_bounds__(256) void qkv_gemm_kernel(
    const float* __restrict__ x, const float* __restrict__ Wa,
    const float* __restrict__ ba)
{
    gemm_body(x, Wa, ba, g_qkv, BB * TT, 3 * CC, CC);
}

__global__ __launch_bounds__(256) void proj_gemm_kernel(
    const float* __restrict__ Wp, const float* __restrict__ bp,
    float* __restrict__ out)
{
    gemm_body(g_y, Wp, bp, out, BB * TT, CC, CC);
}

// ---------------- causal flash attention ------------------------------------
// grid: (T/128, NH, B); block: 128 threads, 1 query row per thread.
// K/V tiles of 64 rows in SMEM; q row + output in registers; online softmax
// over 16-key chunks.
#define AT_QROWS 128
#define AT_KTILE 64

__global__ __launch_bounds__(128) void attn_kernel()
{
    const int qt  = blockIdx.x;
    const int h   = blockIdx.y;
    const int b   = blockIdx.z;
    const int tid = threadIdx.x;
    const int qg  = qt * AT_QROWS + tid;   // global query row (0..T-1)

    __shared__ float4 kx[AT_KTILE][HD / 4];
    __shared__ float4 vx[AT_KTILE][HD / 4];

    const float* qptr = g_qkv + ((size_t)(b * TT + qg)) * 3 * CC + h * HD;
    float4 q[HD / 4];
    #pragma unroll
    for (int i = 0; i < HD / 4; i++) q[i] = ((const float4*)qptr)[i];

    float o[HD];
    #pragma unroll
    for (int d = 0; d < HD; d++) o[d] = 0.f;
    float m = -1e30f, l = 0.f;
    const float scale = 0.125f;   // 1/sqrt(64)

    const int ktiles = 2 * qt + 2;   // cover keys 0..qt*128+127
    for (int kt = 0; kt < ktiles; kt++) {
        const int k0 = kt * AT_KTILE;
        __syncthreads();   // protect previous tile reads
        const float* kbase = g_qkv + ((size_t)(b * TT + k0)) * 3 * CC + CC + h * HD;
        const float* vbase = kbase + CC;
        #pragma unroll
        for (int i = 0; i < 8; i++) {
            const int lin = tid + i * 128;        // 0..1023 float4 slots
            const int r   = lin >> 4;
            const int c4  = lin & 15;
            kx[r][c4] = *(const float4*)(kbase + (size_t)r * 3 * CC + c4 * 4);
            vx[r][c4] = *(const float4*)(vbase + (size_t)r * 3 * CC + c4 * 4);
        }
        __syncthreads();

        #pragma unroll 1
        for (int ch = 0; ch < 4; ch++) {          // 4 chunks of 16 keys
            float s[16];
            #pragma unroll
            for (int j = 0; j < 16; j++) {
                const int kr = ch * 16 + j;
                float ax = 0.f, ay = 0.f, az = 0.f, aw = 0.f;
                #pragma unroll
                for (int d4 = 0; d4 < HD / 4; d4++) {
                    float4 kv = kx[kr][d4];
                    ax += q[d4].x * kv.x;
                    ay += q[d4].y * kv.y;
                    az += q[d4].z * kv.z;
                    aw += q[d4].w * kv.w;
                }
                float sv = ((ax + ay) + (az + aw)) * scale;
                if (k0 + kr > qg) sv = -1e30f;    // causal mask
                s[j] = sv;
            }
            float mc = s[0];
            #pragma unroll
            for (int j = 1; j < 16; j++) mc = fmaxf(mc, s[j]);
            const float mn   = fmaxf(m, mc);
            const float corr = __expf(m - mn);
            float ps = 0.f;
            #pragma unroll
            for (int j = 0; j < 16; j++) { s[j] = __expf(s[j] - mn); ps += s[j]; }
            l = l * corr + ps;
            m = mn;
            #pragma unroll
            for (int d = 0; d < HD; d++) o[d] *= corr;
            #pragma unroll
            for (int j = 0; j < 16; j++) {
                const int kr = ch * 16 + j;
                const float pj = s[j];
                #pragma unroll
                for (int d4 = 0; d4 < HD / 4; d4++) {
                    float4 vv = vx[kr][d4];
                    o[d4 * 4 + 0] += pj * vv.x;
                    o[d4 * 4 + 1] += pj * vv.y;
                    o[d4 * 4 + 2] += pj * vv.z;
                    o[d4 * 4 + 3] += pj * vv.w;
                }
            }
        }
    }

    const float inv = 1.f / l;
    float* yo = g_y + ((size_t)(b * TT + qg)) * CC + h * HD;
    #pragma unroll
    for (int d4 = 0; d4 < HD / 4; d4++) {
        float4 ov;
        ov.x = o[d4 * 4 + 0] * inv;
        ov.y = o[d4 * 4 + 1] * inv;
        ov.z = o[d4 * 4 + 2] * inv;
        ov.w = o[d4 * 4 + 3] * inv;
        ((float4*)yo)[d4] = ov;
    }
}

// ---------------- launch -----------------------------------------------------
extern "C" void kernel_launch(void* const* d_in, const int* in_sizes, int n_in,
                              void* d_out, int out_size)
{
    (void)in_sizes; (void)n_in; (void)out_size;
    const float* x  = (const float*)d_in[0];
    const float* Wa = (const float*)d_in[1];
    const float* ba = (const float*)d_in[2];
    const float* Wp = (const float*)d_in[3];
    const float* bp = (const float*)d_in[4];
    float* out = (float*)d_out;

    // 1) QKV GEMM: [8192,1024]@[1024,3072]+b -> g_qkv
    {
        dim3 grid(3 * CC / GBN, BB * TT / GBM);
        qkv_gemm_kernel<<<grid, 256>>>(x, Wa, ba);
    }
    // 2) causal flash attention: g_qkv -> g_y
    {
        dim3 grid(TT / AT_QROWS, NH, BB);
        attn_kernel<<<grid, 128>>>();
    }
    // 3) proj GEMM: [8192,1024]@[1024,1024]+b -> out
    {
        dim3 grid(CC / GBN, BB * TT / GBM);
        proj_gemm_kernel<<<grid, 256>>>(Wp, bp, out);
    }
}

// round 5
// speedup vs baseline: 2.3005x; 2.3005x over previous
#include <cuda_runtime.h>
#include <cuda_bf16.h>
#include <cstdint>
#include <cstddef>

// Problem constants
#define BB 4
#define TT 2048
#define CC 1024
#define NH 16
#define HD 64
#define MM (BB * TT)          // 8192 rows
#define KK CC                 // 1024 inner dim (both GEMMs)
#define NQKV (3 * CC)         // 3072
#define NPROJ CC              // 1024

// ---------------- scratch (device globals; no allocations allowed) ----------
__device__ float g_qkv[(size_t)MM * NQKV];            // [B*T, 3C] fp32
__device__ float g_y  [(size_t)MM * CC];              // [B*T, C]  fp32
__device__ __nv_bfloat16 g_xh[(size_t)MM * KK];       // x hi/lo  [M,K]
__device__ __nv_bfloat16 g_xl[(size_t)MM * KK];
__device__ __nv_bfloat16 g_yh[(size_t)MM * KK];       // y hi/lo  [M,K]
__device__ __nv_bfloat16 g_yl[(size_t)MM * KK];
__device__ __nv_bfloat16 g_wah[(size_t)NQKV * KK];    // W_attn^T hi/lo [N,K]
__device__ __nv_bfloat16 g_wal[(size_t)NQKV * KK];
__device__ __nv_bfloat16 g_wph[(size_t)NPROJ * KK];   // W_proj^T hi/lo [N,K]
__device__ __nv_bfloat16 g_wpl[(size_t)NPROJ * KK];

// ---------------- PTX helpers (sm_80-portable only!) -------------------------
__device__ __forceinline__ uint32_t smem_to_u32(const void* p) {
    uint32_t a;
    asm("{ .reg .u64 t; cvta.to.shared.u64 t, %1; cvt.u32.u64 %0, t; }" : "=r"(a) : "l"(p));
    return a;
}
__device__ __forceinline__ void cpasync16(uint32_t sm, const void* g) {
    asm volatile("cp.async.ca.shared.global [%0], [%1], 16;" :: "r"(sm), "l"(g));
}
#define CP_COMMIT() asm volatile("cp.async.commit_group;" ::: "memory")
#define CP_WAIT0()  asm volatile("cp.async.wait_group 0;" ::: "memory")

__device__ __forceinline__ void ldmatrix_x4(uint32_t& r0, uint32_t& r1, uint32_t& r2,
                                            uint32_t& r3, uint32_t addr) {
    asm volatile("ldmatrix.sync.aligned.m8n8.x4.shared.b16 {%0,%1,%2,%3}, [%4];"
                 : "=r"(r0), "=r"(r1), "=r"(r2), "=r"(r3) : "r"(addr));
}
__device__ __forceinline__ void ldmatrix_x2(uint32_t& r0, uint32_t& r1, uint32_t addr) {
    asm volatile("ldmatrix.sync.aligned.m8n8.x2.shared.b16 {%0,%1}, [%2];"
                 : "=r"(r0), "=r"(r1) : "r"(addr));
}
__device__ __forceinline__ void mma_bf16(float* c, const uint32_t* a, const uint32_t* b) {
    asm volatile("mma.sync.aligned.m16n8k16.row.col.f32.bf16.bf16.f32 "
                 "{%0,%1,%2,%3}, {%4,%5,%6,%7}, {%8,%9}, {%0,%1,%2,%3};"
                 : "+f"(c[0]), "+f"(c[1]), "+f"(c[2]), "+f"(c[3])
                 : "r"(a[0]), "r"(a[1]), "r"(a[2]), "r"(a[3]), "r"(b[0]), "r"(b[1]));
}

// ---------------- prep kernels ----------------------------------------------
__global__ __launch_bounds__(256) void split_kernel(
    const float* __restrict__ src, __nv_bfloat16* __restrict__ hi,
    __nv_bfloat16* __restrict__ lo, int n4)
{
    int i = blockIdx.x * blockDim.x + threadIdx.x;
    if (i >= n4) return;
    float4 v = ((const float4*)src)[i];
    __nv_bfloat162 h0, h1, l0, l1;
    h0.x = __float2bfloat16(v.x); l0.x = __float2bfloat16(v.x - __bfloat162float(h0.x));
    h0.y = __float2bfloat16(v.y); l0.y = __float2bfloat16(v.y - __bfloat162float(h0.y));
    h1.x = __float2bfloat16(v.z); l1.x = __float2bfloat16(v.z - __bfloat162float(h1.x));
    h1.y = __float2bfloat16(v.w); l1.y = __float2bfloat16(v.w - __bfloat162float(h1.y));
    ((__nv_bfloat162*)hi)[i * 2 + 0] = h0;
    ((__nv_bfloat162*)hi)[i * 2 + 1] = h1;
    ((__nv_bfloat162*)lo)[i * 2 + 0] = l0;
    ((__nv_bfloat162*)lo)[i * 2 + 1] = l1;
}

__global__ __launch_bounds__(256) void transpose_split_kernel(
    const float* __restrict__ W, __nv_bfloat16* __restrict__ Th,
    __nv_bfloat16* __restrict__ Tl, int K, int N)
{
    __shared__ float tile[32][33];
    const int tx = threadIdx.x, ty = threadIdx.y;    // block (32,8)
    const int n0 = blockIdx.x * 32, k0 = blockIdx.y * 32;
    #pragma unroll
    for (int i = 0; i < 32; i += 8)
        tile[ty + i][tx] = W[(size_t)(k0 + ty + i) * N + n0 + tx];
    __syncthreads();
    #pragma unroll
    for (int i = 0; i < 32; i += 8) {
        float v = tile[tx][ty + i];
        __nv_bfloat16 h = __float2bfloat16(v);
        __nv_bfloat16 l = __float2bfloat16(v - __bfloat162float(h));
        size_t o = (size_t)(n0 + ty + i) * K + k0 + tx;
        Th[o] = h; Tl[o] = l;
    }
}

// ---------------- split-bf16 mma.sync GEMM -----------------------------------
// D[m,n] = sum_k A[m,k]*B[n,k] (+bias[n]); A,B pre-split bf16 hi/lo, row-major,
// leading dim K. CTA tile 128x128, BK=32, 8 warps (2Mx4N), warp tile 64x32.
// SMEM: 4 tiles (Ah,Al,Bh,Bl) of [128][40] bf16 (80B stride), double buffered.
#define GST      40                        // smem row stride in bf16 elems
#define GTILE_B  (128 * GST * 2)           // 10240 bytes per tile
#define GSTAGE_B (4 * GTILE_B)             // 40960 bytes per stage
#define GSMEM_TOTAL (2 * GSTAGE_B)         // 81920

__global__ __launch_bounds__(256) void mma_gemm_kernel(
    const __nv_bfloat16* __restrict__ Ah, const __nv_bfloat16* __restrict__ Al,
    const __nv_bfloat16* __restrict__ Bh, const __nv_bfloat16* __restrict__ Bl,
    const float* __restrict__ bias, float* __restrict__ C, int N, int K)
{
    extern __shared__ char smem[];
    const uint32_t sbase = smem_to_u32(smem);
    const int tid = threadIdx.x;
    const int wid = tid >> 5, lane = tid & 31;
    const int m0 = blockIdx.y * 128;
    const int n0 = blockIdx.x * 128;
    const int warp_m = wid >> 2;           // 0..1 -> 64 rows each
    const int warp_n = wid & 3;            // 0..3 -> 32 cols each

    const __nv_bfloat16* gA[2] = { Ah + (size_t)m0 * K, Al + (size_t)m0 * K };
    const __nv_bfloat16* gB[2] = { Bh + (size_t)n0 * K, Bl + (size_t)n0 * K };

    // g2s mapping: per tile 512 x 16B chunks; thread does chunks tid, tid+256
    const int r0c = tid >> 2, c0c = tid & 3;   // chunk tid
    // (chunk tid+256: row r0c+64, same c0c)

    auto issue_stage = [&](int stage, int kof) {
        uint32_t sb = sbase + stage * GSTAGE_B;
        #pragma unroll
        for (int t = 0; t < 4; t++) {
            const __nv_bfloat16* g = (t < 2) ? gA[t] : gB[t - 2];
            uint32_t st = sb + t * GTILE_B;
            cpasync16(st + (uint32_t)(r0c * (GST * 2) + c0c * 16),
                      (const char*)g + (size_t)r0c * K * 2 + kof * 2 + c0c * 16);
            cpasync16(st + (uint32_t)((r0c + 64) * (GST * 2) + c0c * 16),
                      (const char*)g + (size_t)(r0c + 64) * K * 2 + kof * 2 + c0c * 16);
        }
    };

    float acc[4][4][4];
    #pragma unroll
    for (int i = 0; i < 4; i++)
        #pragma unroll
        for (int j = 0; j < 4; j++)
            #pragma unroll
            for (int r = 0; r < 4; r++) acc[i][j][r] = 0.f;

    const int NC = K >> 5;                 // 32 K-chunks
    issue_stage(0, 0);
    CP_COMMIT();

    // ldmatrix address components (within a tile)
    const int a_row = (lane & 15);               // + mt*16 + warp_m*64
    const int a_col = (lane >> 4) * 8;           // + ks*16
    const int b_row = (lane & 7);                // + nt*8 + warp_n*32
    const int b_col = ((lane >> 3) & 1) * 8;     // + ks*16

    for (int kc = 0; kc < NC; kc++) {
        CP_WAIT0();
        __syncthreads();
        const int cur = kc & 1;
        if (kc + 1 < NC) { issue_stage(cur ^ 1, (kc + 1) << 5); CP_COMMIT(); }

        const uint32_t sb = sbase + cur * GSTAGE_B;
        const uint32_t sAh = sb;
        const uint32_t sAl = sb + GTILE_B;
        const uint32_t sBh = sb + 2 * GTILE_B;
        const uint32_t sBl = sb + 3 * GTILE_B;

        #pragma unroll
        for (int ks = 0; ks < 2; ks++) {
            const int kcol = ks * 16;
            uint32_t ah[4][4], al[4][4], bh[4][2], bl[4][2];
            #pragma unroll
            for (int mt = 0; mt < 4; mt++) {
                const uint32_t off = (uint32_t)((warp_m * 64 + mt * 16 + a_row) * (GST * 2)
                                                + (kcol + a_col) * 2);
                ldmatrix_x4(ah[mt][0], ah[mt][1], ah[mt][2], ah[mt][3], sAh + off);
                ldmatrix_x4(al[mt][0], al[mt][1], al[mt][2], al[mt][3], sAl + off);
            }
            #pragma unroll
            for (int nt = 0; nt < 4; nt++) {
                const uint32_t off = (uint32_t)((warp_n * 32 + nt * 8 + b_row) * (GST * 2)
                                                + (kcol + b_col) * 2);
                ldmatrix_x2(bh[nt][0], bh[nt][1], sBh + off);
                ldmatrix_x2(bl[nt][0], bl[nt][1], sBl + off);
            }
            #pragma unroll
            for (int mt = 0; mt < 4; mt++)
                #pragma unroll
                for (int nt = 0; nt < 4; nt++) {
                    mma_bf16(acc[mt][nt], ah[mt], bh[nt]);
                    mma_bf16(acc[mt][nt], ah[mt], bl[nt]);
                    mma_bf16(acc[mt][nt], al[mt], bh[nt]);
                }
        }
        __syncthreads();
    }

    // epilogue: acc[mt][nt] regs c0..c3 -> rows m,(m+8), cols n,(n+1)
    const int er = lane >> 2, ec = (lane & 3) * 2;
    #pragma unroll
    for (int mt = 0; mt < 4; mt++) {
        const int mrow = m0 + warp_m * 64 + mt * 16 + er;
        #pragma unroll
        for (int nt = 0; nt < 4; nt++) {
            const int ncol = n0 + warp_n * 32 + nt * 8 + ec;
            float2 v0 = { acc[mt][nt][0] + bias[ncol], acc[mt][nt][1] + bias[ncol + 1] };
            float2 v1 = { acc[mt][nt][2] + bias[ncol], acc[mt][nt][3] + bias[ncol + 1] };
            *(float2*)(C + (size_t)mrow * N + ncol) = v0;
            *(float2*)(C + (size_t)(mrow + 8) * N + ncol) = v1;
        }
    }
}

// ---------------- causal flash attention (unchanged) -------------------------
#define AT_QROWS 128
#define AT_KTILE 64

__global__ __launch_bounds__(128) void attn_kernel()
{
    const int qt  = blockIdx.x;
    const int h   = blockIdx.y;
    const int b   = blockIdx.z;
    const int tid = threadIdx.x;
    const int qg  = qt * AT_QROWS + tid;

    __shared__ float4 kx[AT_KTILE][HD / 4];
    __shared__ float4 vx[AT_KTILE][HD / 4];

    const float* qptr = g_qkv + ((size_t)(b * TT + qg)) * 3 * CC + h * HD;
    float4 q[HD / 4];
    #pragma unroll
    for (int i = 0; i < HD / 4; i++) q[i] = ((const float4*)qptr)[i];

    float o[HD];
    #pragma unroll
    for (int d = 0; d < HD; d++) o[d] = 0.f;
    float m = -1e30f, l = 0.f;
    const float scale = 0.125f;

    const int ktiles = 2 * qt + 2;
    for (int kt = 0; kt < ktiles; kt++) {
        const int k0 = kt * AT_KTILE;
        __syncthreads();
        const float* kbase = g_qkv + ((size_t)(b * TT + k0)) * 3 * CC + CC + h * HD;
        const float* vbase = kbase + CC;
        #pragma unroll
        for (int i = 0; i < 8; i++) {
            const int lin = tid + i * 128;
            const int r   = lin >> 4;
            const int c4  = lin & 15;
            kx[r][c4] = *(const float4*)(kbase + (size_t)r * 3 * CC + c4 * 4);
            vx[r][c4] = *(const float4*)(vbase + (size_t)r * 3 * CC + c4 * 4);
        }
        __syncthreads();

        #pragma unroll 1
        for (int ch = 0; ch < 4; ch++) {
            float s[16];
            #pragma unroll
            for (int j = 0; j < 16; j++) {
                const int kr = ch * 16 + j;
                float ax = 0.f, ay = 0.f, az = 0.f, aw = 0.f;
                #pragma unroll
                for (int d4 = 0; d4 < HD / 4; d4++) {
                    float4 kv = kx[kr][d4];
                    ax += q[d4].x * kv.x;
                    ay += q[d4].y * kv.y;
                    az += q[d4].z * kv.z;
                    aw += q[d4].w * kv.w;
                }
                float sv = ((ax + ay) + (az + aw)) * scale;
                if (k0 + kr > qg) sv = -1e30f;
                s[j] = sv;
            }
            float mc = s[0];
            #pragma unroll
            for (int j = 1; j < 16; j++) mc = fmaxf(mc, s[j]);
            const float mn   = fmaxf(m, mc);
            const float corr = __expf(m - mn);
            float ps = 0.f;
            #pragma unroll
            for (int j = 0; j < 16; j++) { s[j] = __expf(s[j] - mn); ps += s[j]; }
            l = l * corr + ps;
            m = mn;
            #pragma unroll
            for (int d = 0; d < HD; d++) o[d] *= corr;
            #pragma unroll
            for (int j = 0; j < 16; j++) {
                const int kr = ch * 16 + j;
                const float pj = s[j];
                #pragma unroll
                for (int d4 = 0; d4 < HD / 4; d4++) {
                    float4 vv = vx[kr][d4];
                    o[d4 * 4 + 0] += pj * vv.x;
                    o[d4 * 4 + 1] += pj * vv.y;
                    o[d4 * 4 + 2] += pj * vv.z;
                    o[d4 * 4 + 3] += pj * vv.w;
                }
            }
        }
    }

    const float inv = 1.f / l;
    float* yo = g_y + ((size_t)(b * TT + qg)) * CC + h * HD;
    #pragma unroll
    for (int d4 = 0; d4 < HD / 4; d4++) {
        float4 ov;
        ov.x = o[d4 * 4 + 0] * inv;
        ov.y = o[d4 * 4 + 1] * inv;
        ov.z = o[d4 * 4 + 2] * inv;
        ov.w = o[d4 * 4 + 3] * inv;
        ((float4*)yo)[d4] = ov;
    }
}

// ---------------- launch -----------------------------------------------------
extern "C" void kernel_launch(void* const* d_in, const int* in_sizes, int n_in,
                              void* d_out, int out_size)
{
    (void)in_sizes; (void)n_in; (void)out_size;
    const float* x  = (const float*)d_in[0];
    const float* Wa = (const float*)d_in[1];
    const float* ba = (const float*)d_in[2];
    const float* Wp = (const float*)d_in[3];
    const float* bp = (const float*)d_in[4];
    float* out = (float*)d_out;

    cudaFuncSetAttribute(mma_gemm_kernel, cudaFuncAttributeMaxDynamicSharedMemorySize, GSMEM_TOTAL);

    __nv_bfloat16 *xh, *xl, *yh, *yl, *wah, *wal, *wph, *wpl;
    cudaGetSymbolAddress((void**)&xh,  g_xh);  cudaGetSymbolAddress((void**)&xl,  g_xl);
    cudaGetSymbolAddress((void**)&yh,  g_yh);  cudaGetSymbolAddress((void**)&yl,  g_yl);
    cudaGetSymbolAddress((void**)&wah, g_wah); cudaGetSymbolAddress((void**)&wal, g_wal);
    cudaGetSymbolAddress((void**)&wph, g_wph); cudaGetSymbolAddress((void**)&wpl, g_wpl);
    float *qkv, *y;
    cudaGetSymbolAddress((void**)&qkv, g_qkv); cudaGetSymbolAddress((void**)&y, g_y);

    // 1) split x -> bf16 hi/lo
    {
        int n4 = MM * KK / 4;
        split_kernel<<<(n4 + 255) / 256, 256>>>(x, xh, xl, n4);
    }
    // 2) transpose+split weights
    {
        dim3 blk(32, 8);
        transpose_split_kernel<<<dim3(NQKV / 32, KK / 32), blk>>>(Wa, wah, wal, KK, NQKV);
        transpose_split_kernel<<<dim3(NPROJ / 32, KK / 32), blk>>>(Wp, wph, wpl, KK, NPROJ);
    }
    // 3) QKV GEMM (mma.sync): [8192,1024]@[1024,3072]+b -> g_qkv
    mma_gemm_kernel<<<dim3(NQKV / 128, MM / 128), 256, GSMEM_TOTAL>>>(
        xh, xl, wah, wal, ba, qkv, NQKV, KK);
    // 4) causal flash attention: g_qkv -> g_y
    attn_kernel<<<dim3(TT / AT_QROWS, NH, BB), 128>>>();
    // 5) split y -> bf16 hi/lo
    {
        int n4 = MM * KK / 4;
        split_kernel<<<(n4 + 255) / 256, 256>>>(y, yh, yl, n4);
    }
    // 6) proj GEMM (mma.sync): [8192,1024]@[1024,1024]+b -> out
    mma_gemm_kernel<<<dim3(NPROJ / 128, MM / 128), 256, GSMEM_TOTAL>>>(
        yh, yl, wph, wpl, bp, out, NPROJ, KK);
}